// round 3
// baseline (speedup 1.0000x reference)
#include <cuda_runtime.h>
#include <math.h>

#define BATCH 16
#define NSAMP 72000
#define TOTF  2039   // 17+33+65+129+257+513+1025

__device__ double g_s1[TOTF];
__device__ double g_s2[TOTF];

__host__ __device__ constexpr int ilog2c(int n) { return (n <= 1) ? 0 : 1 + ilog2c(n >> 1); }

// Blocks runtime constant folding while preserving exact double bits.
__device__ __forceinline__ double opaque_d(double x) { volatile double t = x; return t; }

// One block = FPB concurrent frames, grid-stride over all B*T frames of this scale.
// z = x + i*x_hat packed complex FFT (in-place radix-2 DIT, bit-reversed load),
// unpack both magnitudes, accumulate |d| and d^2 per frequency in registers,
// reduce via shared, then double atomics to global.
template<int NFFT, int OFF>
__global__ void __launch_bounds__(256)
stft_kernel(const float* __restrict__ x, const float* __restrict__ xh) {
    constexpr int HOP   = NFFT / 4;
    constexpr int PAD   = NFFT / 2;
    constexpr int T     = 1 + NSAMP / HOP;
    constexpr int TOTAL = BATCH * T;
    constexpr int F     = NFFT / 2 + 1;
    constexpr int LOG2N = ilog2c(NFFT);
    constexpr int FPB   = (NFFT <= 512) ? (512 / NFFT) : 1;   // frames per block
    constexpr int TPB   = 256;
    constexpr int TPF   = TPB / FPB;                          // threads per frame
    constexpr int BPT   = (NFFT / 2) / TPF;                   // butterflies/thread
    constexpr int KPT   = BPT + 1;                            // max freqs/thread
    constexpr int SPT   = NFFT / TPF;                         // samples/thread (load)

    __shared__ float2 buf[FPB * NFFT];
    __shared__ float2 tw[NFFT / 2];
    __shared__ float  win[NFFT];
    __shared__ float  red1[F];
    __shared__ float  red2[F];

    const int tid  = threadIdx.x;
    const int slot = tid / TPF;
    const int ltid = tid % TPF;

    // Twiddles: tw[t] = exp(-2*pi*i*t/N). Window: periodic hann * 1/sqrt(sum w^2),
    // sum w^2 = 0.375*N exactly for periodic hann.
    const float rnorm = rsqrtf(0.375f * (float)NFFT);
    for (int t = tid; t < NFFT / 2; t += TPB) {
        float s, c;
        sincospif(2.0f * (float)t / (float)NFFT, &s, &c);
        tw[t] = make_float2(c, -s);
    }
    for (int t = tid; t < NFFT; t += TPB) {
        win[t] = (0.5f - 0.5f * cospif(2.0f * (float)t / (float)NFFT)) * rnorm;
    }
    for (int t = tid; t < F; t += TPB) { red1[t] = 0.0f; red2[t] = 0.0f; }

    float acc1[KPT], acc2[KPT];
#pragma unroll
    for (int r = 0; r < KPT; r++) { acc1[r] = 0.0f; acc2[r] = 0.0f; }

    __syncthreads();

    for (int base = blockIdx.x * FPB; base < TOTAL; base += gridDim.x * FPB) {
        const int gf = base + slot;
        const bool valid = (gf < TOTAL);

        if (valid) {
            const int b  = gf / T;
            const int t0 = gf - b * T;
            const int start = t0 * HOP - PAD;
            const float* xb  = x  + b * NSAMP;
            const float* xhb = xh + b * NSAMP;
#pragma unroll
            for (int r = 0; r < SPT; r++) {
                const int tt = ltid + r * TPF;
                int s = start + tt;
                s = (s < 0) ? -s : s;                       // reflect left
                s = (s >= NSAMP) ? (2 * NSAMP - 2 - s) : s; // reflect right
                const float wv = win[tt];
                const int rev = (int)(__brev((unsigned)tt) >> (32 - LOG2N));
                buf[slot * NFFT + rev] = make_float2(xb[s] * wv, xhb[s] * wv);
            }
        }
        __syncthreads();

        // In-place radix-2 DIT (bit-reversed input -> natural output)
#pragma unroll
        for (int len = 2; len <= NFFT; len <<= 1) {
            const int half = len >> 1;
#pragma unroll
            for (int r = 0; r < BPT; r++) {
                const int idx = ltid + r * TPF;        // [0, NFFT/2)
                const int j   = idx & (half - 1);
                const int g   = idx / half;
                const int p1  = slot * NFFT + g * len + j;
                const float2 a  = buf[p1];
                const float2 b2 = buf[p1 + half];
                const float2 w  = tw[j * (NFFT / len)];
                const float2 t  = make_float2(b2.x * w.x - b2.y * w.y,
                                              b2.x * w.y + b2.y * w.x);
                buf[p1]        = make_float2(a.x + t.x, a.y + t.y);
                buf[p1 + half] = make_float2(a.x - t.x, a.y - t.y);
            }
            __syncthreads();
        }

        // Unpack X (from x) and Xh (from x_hat), accumulate stats
        if (valid) {
#pragma unroll
            for (int r = 0; r < KPT; r++) {
                const int k = ltid + r * TPF;
                if (k <= NFFT / 2) {
                    const float2 zk = buf[slot * NFFT + k];
                    const float2 zn = buf[slot * NFFT + ((NFFT - k) & (NFFT - 1))];
                    const float ar = 0.5f * (zk.x + zn.x);
                    const float ai = 0.5f * (zk.y - zn.y);
                    const float br = 0.5f * (zk.y + zn.y);
                    const float bi = 0.5f * (zn.x - zk.x);
                    const float magA = sqrtf(ar * ar + ai * ai);
                    const float magB = sqrtf(br * br + bi * bi);
                    const float d = magB - magA;          // |Xh| - |X|
                    acc1[r] += fabsf(d);
                    acc2[r] += d * d;
                }
            }
        }
        __syncthreads();   // protect buf before next load
    }

    // Block reduce: registers -> shared float
#pragma unroll
    for (int r = 0; r < KPT; r++) {
        const int k = ltid + r * TPF;
        if (k <= NFFT / 2) {
            atomicAdd(&red1[k], acc1[r]);
            atomicAdd(&red2[k], acc2[r]);
        }
    }
    __syncthreads();

    for (int k = tid; k < F; k += TPB) {
        atomicAdd(&g_s1[OFF + k], (double)red1[k]);
        atomicAdd(&g_s2[OFF + k], (double)red2[k]);
    }
}

// Mel-band combine. One thread per (scale, band-candidate). Band m support =
// bins f with f_pts[m] < f*step < f_pts[m+2] (strict). All interior decisions
// have >=1e-3 relative margins (safe in double). The ONLY knife-edge is the
// Nyquist bin (freq == 12000.0 exactly) vs f_pts[65] (a log10/pow round-trip
// of 12000, = 12000 +- few ulp, libm-rounding dependent). We reproduce the
// previous kernel's decision with the identical runtime-pow expression and
// take the OPPOSITE, since that decision was evidently the wrong side.
__global__ void loss_kernel(float* out) {
    __shared__ int    nb[7];
    __shared__ double sl[7];
    const int tid = threadIdx.x;
    if (tid < 7) { nb[tid] = 0; sl[tid] = 0.0; }
    __syncthreads();

    const int scale = tid >> 6;
    const int m     = tid & 63;

    if (scale < 7) {
        const int offs[7] = {0, 17, 50, 115, 244, 501, 1014};
        const int Ts[7]   = {9001, 4501, 2251, 1126, 563, 282, 141};
        const int nfft = 32 << scale;
        const int F = nfft / 2 + 1;
        const double step = 12000.0 / (double)(F - 1);
        const double melmax = 2595.0 * log10(1.0 + 12000.0 / 700.0);

        // Reproduce old kernel's f_pts[65] with the same runtime libdevice pow
        // (opaque blocks compile-time folding, preserves bits), then flip.
        const double e65  = (melmax * 65.0 / 65.0) / 2595.0;
        const double hi65 = 700.0 * (pow(10.0, opaque_d(e65)) - 1.0);
        const bool   nyq_in = !(hi65 > 12000.0);

        int a[2], b[2];   // [0] = band m, [1] = band m-1
        for (int q = 0; q < 2; q++) {
            const int mm = m - q;
            if (mm < 0) { a[q] = 0; b[q] = 0; continue; }
            const double lo = 700.0 * (pow(10.0, opaque_d(melmax * (double)mm / 65.0) / 2595.0) - 1.0);
            int a0 = (int)floor(lo / step); if ((double)a0 * step <= lo) a0++;  // first f: f*step > lo
            if (a0 < 0) a0 = 0;
            int b0;
            if (mm + 2 == 65) {
                // Top band: bins F-2 and below are always < hi; Nyquist decided by flip.
                b0 = nyq_in ? F : (F - 1);
            } else {
                const double hi = 700.0 * (pow(10.0, opaque_d(melmax * (double)(mm + 2) / 65.0) / 2595.0) - 1.0);
                b0 = (int)floor(hi / step); if ((double)b0 * step <  hi) b0++;  // last f+1: f*step < hi
                if (b0 > F) b0 = F;
            }
            a[q] = a0; b[q] = b0;
        }
        const bool nonempty = (b[0] > a[0]);
        const bool dup = (m > 0) && (a[0] == a[1]) && (b[0] == b[1]) && nonempty;
        if (nonempty && !dup) {
            atomicAdd(&nb[scale], 1);
            double s1 = 0.0, s2 = 0.0;
            for (int f = a[0]; f < b[0]; f++) {
                s1 += g_s1[offs[scale] + f];
                s2 += g_s2[offs[scale] + f];
            }
            const double cnt = (double)(b[0] - a[0]) * (double)BATCH * (double)Ts[scale];
            const double val = s1 / cnt + sqrt(s2 / cnt + 1e-8);
            atomicAdd(&sl[scale], val);
        }
    }
    __syncthreads();

    if (tid == 0) {
        double tot = 0.0;
        for (int s = 0; s < 7; s++) tot += sl[s] / (double)nb[s];
        out[0] = (float)(tot / 7.0);
    }
}

extern "C" void kernel_launch(void* const* d_in, const int* in_sizes, int n_in,
                              void* d_out, int out_size) {
    const float* xh = (const float*)d_in[0];   // x_hat
    const float* x  = (const float*)d_in[1];   // x
    // (|Xh-X| and (Xh-X)^2 are symmetric under swap, so ordering is safe either way)

    void *p1 = nullptr, *p2 = nullptr;
    cudaGetSymbolAddress(&p1, g_s1);
    cudaGetSymbolAddress(&p2, g_s2);
    cudaMemsetAsync(p1, 0, TOTF * sizeof(double));
    cudaMemsetAsync(p2, 0, TOTF * sizeof(double));

    stft_kernel<  32,    0><<<740, 256>>>(x, xh);
    stft_kernel<  64,   17><<<740, 256>>>(x, xh);
    stft_kernel< 128,   50><<<740, 256>>>(x, xh);
    stft_kernel< 256,  115><<<740, 256>>>(x, xh);
    stft_kernel< 512,  244><<<740, 256>>>(x, xh);
    stft_kernel<1024,  501><<<740, 256>>>(x, xh);
    stft_kernel<2048, 1014><<<740, 256>>>(x, xh);

    loss_kernel<<<1, 512>>>((float*)d_out);
}

// round 4
// speedup vs baseline: 1.6324x; 1.6324x over previous
#include <cuda_runtime.h>
#include <math.h>

#define BATCH 16
#define NSAMP 72000
#define TOTF  2039   // 17+33+65+129+257+513+1025

__device__ double g_s1[TOTF];
__device__ double g_s2[TOTF];

__host__ __device__ constexpr int ilog2c(int n) { return (n <= 1) ? 0 : 1 + ilog2c(n >> 1); }

// Blocks runtime constant folding while preserving exact double bits.
__device__ __forceinline__ double opaque_d(double x) { volatile double t = x; return t; }

__device__ __forceinline__ float2 cadd(float2 a, float2 b) { return make_float2(a.x + b.x, a.y + b.y); }
__device__ __forceinline__ float2 csub(float2 a, float2 b) { return make_float2(a.x - b.x, a.y - b.y); }
__device__ __forceinline__ float2 cmul(float2 a, float2 b) {
    return make_float2(a.x * b.x - a.y * b.y, a.x * b.y + a.y * b.x);
}

// Packed complex FFT (z = x + i*x_hat) over all frames of one scale.
// Radix-4 (fused 2x radix-2) stages; first two stages fused into the windowed
// load (trivial twiddles); leftover radix-2 stage for odd log2(N).
// buf accesses go through an XOR bank swizzle to kill the bit-reversal-store
// and small-stride-stage conflicts.
template<int NFFT, int OFF>
__global__ void __launch_bounds__(256)
stft_kernel(const float* __restrict__ x, const float* __restrict__ xh) {
    constexpr int HOP   = NFFT / 4;
    constexpr int PAD   = NFFT / 2;
    constexpr int T     = 1 + NSAMP / HOP;
    constexpr int TOTAL = BATCH * T;
    constexpr int F     = NFFT / 2 + 1;
    constexpr int LOG2N = ilog2c(NFFT);
    constexpr int TPB   = 256;
    constexpr int Q     = NFFT / 4;                    // radix-4 butterflies per frame
    constexpr int FPB   = (Q < TPB) ? (TPB / Q) : 1;   // frames per block
    constexpr int TPF   = TPB / FPB;                   // threads per frame
    constexpr int BPT4  = Q / TPF;                     // fused butterflies per thread
    constexpr int KPT   = (F + TPF - 1) / TPF;         // freq bins per thread (unpack)
    constexpr int BUFSZ = FPB * NFFT;
    constexpr int S     = ilog2c(BUFSZ) - 4;

    __shared__ float2 buf[BUFSZ];
    __shared__ float2 tw[NFFT / 2];
    __shared__ float  win[NFFT];
    __shared__ float  red1[F];
    __shared__ float  red2[F];

    const int tid  = threadIdx.x;
    const int slot = tid / TPF;
    const int ltid = tid % TPF;

    // Bank swizzle: bijective (modifies only bits 0-3 by a function of bits>=4).
    auto sw = [](int i) { return i ^ (((i >> S) ^ (i >> 4)) & 15); };

    // Twiddles: tw[t] = exp(-2*pi*i*t/N). Window: periodic hann / sqrt(0.375*N).
    const float rnorm = rsqrtf(0.375f * (float)NFFT);
    for (int t = tid; t < NFFT / 2; t += TPB) {
        float s, c;
        sincospif(2.0f * (float)t / (float)NFFT, &s, &c);
        tw[t] = make_float2(c, -s);
    }
    for (int t = tid; t < NFFT; t += TPB) {
        win[t] = (0.5f - 0.5f * cospif(2.0f * (float)t / (float)NFFT)) * rnorm;
    }
    for (int t = tid; t < F; t += TPB) { red1[t] = 0.0f; red2[t] = 0.0f; }

    float acc1[KPT], acc2[KPT];
#pragma unroll
    for (int r = 0; r < KPT; r++) { acc1[r] = 0.0f; acc2[r] = 0.0f; }

    __syncthreads();

    for (int base = blockIdx.x * FPB; base < TOTAL; base += gridDim.x * FPB) {
        const int gf = base + slot;
        const bool valid = (gf < TOTAL);

        // Load + window + first fused radix-4 stage (stages len=2,4; twiddles = 1).
        // Thread's coalesced read base idx maps to write-butterfly g = brev(idx).
        if (valid) {
            const int b  = gf / T;
            const int t0 = gf - b * T;
            const int start = t0 * HOP - PAD;
            const float* xb  = x  + b * NSAMP;
            const float* xhb = xh + b * NSAMP;
#pragma unroll
            for (int r = 0; r < BPT4; r++) {
                const int idx = ltid + r * TPF;                       // [0, N/4)
                const int g   = (int)(__brev((unsigned)idx) >> (32 - (LOG2N - 2)));
                float2 a[4];
                constexpr int offs4[4] = {0, NFFT / 2, NFFT / 4, 3 * NFFT / 4};
#pragma unroll
                for (int k = 0; k < 4; k++) {
                    const int tt = idx + offs4[k];
                    int s = start + tt;
                    s = (s < 0) ? -s : s;                        // reflect left
                    s = (s >= NSAMP) ? (2 * NSAMP - 2 - s) : s;  // reflect right
                    const float wv = win[tt];
                    a[k] = make_float2(xb[s] * wv, xhb[s] * wv);
                }
                const float2 c0 = cadd(a[0], a[1]), c1 = csub(a[0], a[1]);
                const float2 c2 = cadd(a[2], a[3]), c3 = csub(a[2], a[3]);
                const int wb = slot * NFFT + 4 * g;
                buf[sw(wb + 0)] = cadd(c0, c2);
                buf[sw(wb + 2)] = csub(c0, c2);
                buf[sw(wb + 1)] = make_float2(c1.x + c3.y, c1.y - c3.x);  // c1 - i*c3
                buf[sw(wb + 3)] = make_float2(c1.x - c3.y, c1.y + c3.x);  // c1 + i*c3
            }
        }
        __syncthreads();

        // Fused radix-4 stages: pair (len=L, len=2L) for L = 8, 32, 128, 512...
#pragma unroll
        for (int L = 8; 2 * L <= NFFT; L *= 4) {
#pragma unroll
            for (int r = 0; r < BPT4; r++) {
                const int idx = ltid + r * TPF;              // [0, N/4)
                const int j   = idx & (L / 2 - 1);
                const int g   = idx / (L / 2);
                const int p   = slot * NFFT + g * (2 * L) + j;
                float2 a0 = buf[sw(p)];
                float2 a1 = buf[sw(p + L / 2)];
                float2 a2 = buf[sw(p + L)];
                float2 a3 = buf[sw(p + 3 * L / 2)];
                const float2 t1 = tw[j * (NFFT / L)];        // w_L^j
                const float2 t2 = tw[j * (NFFT / (2 * L))];  // w_{2L}^j
                const float2 u1 = cmul(t1, a1), u3 = cmul(t1, a3);
                const float2 c0 = cadd(a0, u1), c1 = csub(a0, u1);
                const float2 c2 = cadd(a2, u3), c3 = csub(a2, u3);
                const float2 v2 = cmul(t2, c2), v3 = cmul(t2, c3);
                buf[sw(p)]             = cadd(c0, v2);
                buf[sw(p + L)]         = csub(c0, v2);
                buf[sw(p + L / 2)]     = make_float2(c1.x + v3.y, c1.y - v3.x);  // c1 - i*v3
                buf[sw(p + 3 * L / 2)] = make_float2(c1.x - v3.y, c1.y + v3.x);  // c1 + i*v3
            }
            __syncthreads();
        }

        // Leftover radix-2 stage (len = N) for odd log2(N).
        if constexpr (LOG2N & 1) {
#pragma unroll
            for (int r = 0; r < 2 * BPT4; r++) {
                const int idx = ltid + r * TPF;              // [0, N/2)
                const int p = slot * NFFT + idx;
                const float2 a  = buf[sw(p)];
                const float2 b2 = buf[sw(p + NFFT / 2)];
                const float2 t  = cmul(tw[idx], b2);
                buf[sw(p)]            = cadd(a, t);
                buf[sw(p + NFFT / 2)] = csub(a, t);
            }
            __syncthreads();
        }

        // Unpack X (from x) and Xh (from x_hat), accumulate stats
        if (valid) {
#pragma unroll
            for (int r = 0; r < KPT; r++) {
                const int k = ltid + r * TPF;
                if (k <= NFFT / 2) {
                    const float2 zk = buf[sw(slot * NFFT + k)];
                    const float2 zn = buf[sw(slot * NFFT + ((NFFT - k) & (NFFT - 1)))];
                    const float ar = 0.5f * (zk.x + zn.x);
                    const float ai = 0.5f * (zk.y - zn.y);
                    const float br = 0.5f * (zk.y + zn.y);
                    const float bi = 0.5f * (zn.x - zk.x);
                    const float magA = sqrtf(ar * ar + ai * ai);
                    const float magB = sqrtf(br * br + bi * bi);
                    const float d = magB - magA;          // |Xh| - |X|
                    acc1[r] += fabsf(d);
                    acc2[r] += d * d;
                }
            }
        }
        __syncthreads();   // protect buf before next load
    }

    // Block reduce: registers -> shared float
#pragma unroll
    for (int r = 0; r < KPT; r++) {
        const int k = ltid + r * TPF;
        if (k <= NFFT / 2) {
            atomicAdd(&red1[k], acc1[r]);
            atomicAdd(&red2[k], acc2[r]);
        }
    }
    __syncthreads();

    for (int k = tid; k < F; k += TPB) {
        atomicAdd(&g_s1[OFF + k], (double)red1[k]);
        atomicAdd(&g_s2[OFF + k], (double)red2[k]);
    }
}

// Mel-band combine. One thread per (scale, band-candidate). Band m support =
// bins f with f_pts[m] < f*step < f_pts[m+2] (strict). All interior decisions
// have >=1e-3 relative margins (safe in double). The ONLY knife-edge is the
// Nyquist bin (freq == 12000.0 exactly) vs f_pts[65] (a log10/pow round-trip
// of 12000, = 12000 +- few ulp, libm-rounding dependent). We reproduce the
// libdevice decision and take the OPPOSITE (matches numpy; verified rel_err=0).
__global__ void loss_kernel(float* out) {
    __shared__ int    nb[7];
    __shared__ double sl[7];
    const int tid = threadIdx.x;
    if (tid < 7) { nb[tid] = 0; sl[tid] = 0.0; }
    __syncthreads();

    const int scale = tid >> 6;
    const int m     = tid & 63;

    if (scale < 7) {
        const int offs[7] = {0, 17, 50, 115, 244, 501, 1014};
        const int Ts[7]   = {9001, 4501, 2251, 1126, 563, 282, 141};
        const int nfft = 32 << scale;
        const int F = nfft / 2 + 1;
        const double step = 12000.0 / (double)(F - 1);
        const double melmax = 2595.0 * log10(1.0 + 12000.0 / 700.0);

        const double e65  = (melmax * 65.0 / 65.0) / 2595.0;
        const double hi65 = 700.0 * (pow(10.0, opaque_d(e65)) - 1.0);
        const bool   nyq_in = !(hi65 > 12000.0);

        int a[2], b[2];   // [0] = band m, [1] = band m-1
        for (int q = 0; q < 2; q++) {
            const int mm = m - q;
            if (mm < 0) { a[q] = 0; b[q] = 0; continue; }
            const double lo = 700.0 * (pow(10.0, opaque_d(melmax * (double)mm / 65.0) / 2595.0) - 1.0);
            int a0 = (int)floor(lo / step); if ((double)a0 * step <= lo) a0++;  // first f: f*step > lo
            if (a0 < 0) a0 = 0;
            int b0;
            if (mm + 2 == 65) {
                b0 = nyq_in ? F : (F - 1);
            } else {
                const double hi = 700.0 * (pow(10.0, opaque_d(melmax * (double)(mm + 2) / 65.0) / 2595.0) - 1.0);
                b0 = (int)floor(hi / step); if ((double)b0 * step <  hi) b0++;  // last f+1: f*step < hi
                if (b0 > F) b0 = F;
            }
            a[q] = a0; b[q] = b0;
        }
        const bool nonempty = (b[0] > a[0]);
        const bool dup = (m > 0) && (a[0] == a[1]) && (b[0] == b[1]) && nonempty;
        if (nonempty && !dup) {
            atomicAdd(&nb[scale], 1);
            double s1 = 0.0, s2 = 0.0;
            for (int f = a[0]; f < b[0]; f++) {
                s1 += g_s1[offs[scale] + f];
                s2 += g_s2[offs[scale] + f];
            }
            const double cnt = (double)(b[0] - a[0]) * (double)BATCH * (double)Ts[scale];
            const double val = s1 / cnt + sqrt(s2 / cnt + 1e-8);
            atomicAdd(&sl[scale], val);
        }
    }
    __syncthreads();

    if (tid == 0) {
        double tot = 0.0;
        for (int s = 0; s < 7; s++) tot += sl[s] / (double)nb[s];
        out[0] = (float)(tot / 7.0);
    }
}

extern "C" void kernel_launch(void* const* d_in, const int* in_sizes, int n_in,
                              void* d_out, int out_size) {
    const float* xh = (const float*)d_in[0];   // x_hat
    const float* x  = (const float*)d_in[1];   // x

    void *p1 = nullptr, *p2 = nullptr;
    cudaGetSymbolAddress(&p1, g_s1);
    cudaGetSymbolAddress(&p2, g_s2);
    cudaMemsetAsync(p1, 0, TOTF * sizeof(double));
    cudaMemsetAsync(p2, 0, TOTF * sizeof(double));

    stft_kernel<  32,    0><<<740, 256>>>(x, xh);
    stft_kernel<  64,   17><<<740, 256>>>(x, xh);
    stft_kernel< 128,   50><<<740, 256>>>(x, xh);
    stft_kernel< 256,  115><<<740, 256>>>(x, xh);
    stft_kernel< 512,  244><<<740, 256>>>(x, xh);
    stft_kernel<1024,  501><<<740, 256>>>(x, xh);
    stft_kernel<2048, 1014><<<740, 256>>>(x, xh);

    loss_kernel<<<1, 512>>>((float*)d_out);
}